// round 11
// baseline (speedup 1.0000x reference)
#include <cuda_runtime.h>
#include <cstddef>
#include <cstdint>

#define B_   128
#define T_   1024
#define NI_  64
#define NH_  512
#define DT_C 0.01f

#define S_   16    // N-slices per batch group (CTAs per sync group)
#define NS_  32    // hidden cols per slice
#define G_   8     // batch groups
#define MG_  16    // batch rows per group

// __device__ scratch (allocation-free rule)
__device__ float g_i2h[(size_t)B_ * T_ * NH_];     // tanh(x @ x2h), [B][T][NH]
__device__ float g_hyT[G_][NH_][MG_];              // hy exchange, transposed [k][m]
__device__ float g_zT [G_][NH_][MG_];              // z  exchange, transposed [k][m]
__device__ int   g_flagH[G_][S_];
__device__ int   g_flagZ[G_][S_];

// ---- scoped release/acquire flag ops (generic addresses; no atomics) ----
__device__ __forceinline__ void st_release_gpu(int* p, int v) {
    asm volatile("st.release.gpu.b32 [%0], %1;" :: "l"(p), "r"(v) : "memory");
}
__device__ __forceinline__ int ld_acquire_gpu(const int* p) {
    int v;
    asm volatile("ld.acquire.gpu.b32 %0, [%1];" : "=r"(v) : "l"(p) : "memory");
    return v;
}

// ---------------------------------------------------------------------------
// i2h = tanh(x @ x2h).  x: [B*T, 64], x2h: [64, 512].
// Block (0,0) also resets the scan flags (runs before k_scan, stream order).
// ---------------------------------------------------------------------------
__global__ __launch_bounds__(256) void k_i2h(const float* __restrict__ x,
                                             const float* __restrict__ x2h) {
    __shared__ float xsT[64][64];
    __shared__ float ws[64][64];
    int row0 = blockIdx.y * 64;
    int col0 = blockIdx.x * 64;
    int tid  = threadIdx.x;

    if (blockIdx.x == 0 && blockIdx.y == 0 && tid < G_ * S_) {
        ((int*)g_flagH)[tid] = 0;
        ((int*)g_flagZ)[tid] = 0;
    }

    const float4* xsrc = reinterpret_cast<const float4*>(x + (size_t)row0 * NI_);
    for (int i = tid; i < 1024; i += 256) {
        float4 v = xsrc[i];
        int m = i >> 4;
        int k = (i & 15) * 4;
        xsT[k + 0][m] = v.x; xsT[k + 1][m] = v.y;
        xsT[k + 2][m] = v.z; xsT[k + 3][m] = v.w;
    }
    for (int i = tid; i < 1024; i += 256) {
        int k = i >> 4;
        int c = (i & 15) * 4;
        float4 v = *reinterpret_cast<const float4*>(x2h + (size_t)k * NH_ + col0 + c);
        *reinterpret_cast<float4*>(&ws[k][c]) = v;
    }
    __syncthreads();

    int tx = tid & 15, ty = tid >> 4;
    int m0 = ty * 4, n0 = tx * 4;
    float acc[4][4] = {};
    #pragma unroll 4
    for (int k = 0; k < 64; k++) {
        float4 a = *reinterpret_cast<float4*>(&xsT[k][m0]);
        float4 b = *reinterpret_cast<float4*>(&ws[k][n0]);
        float av[4] = {a.x, a.y, a.z, a.w};
        float bv[4] = {b.x, b.y, b.z, b.w};
        #pragma unroll
        for (int i = 0; i < 4; i++)
            #pragma unroll
            for (int j = 0; j < 4; j++)
                acc[i][j] = fmaf(av[i], bv[j], acc[i][j]);
    }
    #pragma unroll
    for (int i = 0; i < 4; i++) {
        float4 o;
        o.x = tanhf(acc[i][0]); o.y = tanhf(acc[i][1]);
        o.z = tanhf(acc[i][2]); o.w = tanhf(acc[i][3]);
        *reinterpret_cast<float4*>(&g_i2h[(size_t)(row0 + m0 + i) * NH_ + col0 + n0]) = o;
    }
}

// ---------------------------------------------------------------------------
// Persistent scan: 128 CTAs = 8 batch groups x 16 N-slices, 512 threads.
// Weights SMEM-resident all run. Per-step exchange of hy / z through small
// L2 buffers; warp w of each CTA independently polls (acquire) producer w's
// flag and gathers that 2KB slice as soon as it lands (pipelined gather).
// Producer publishes with syncthreads + one st.release.
//
// SMEM (floats): Ws[512][32] @0 | WTs[512][36] @16384 | xbuf[512][20] @34816
//                parts[4][16][36] @45056   -> 189440 bytes dynamic
// ---------------------------------------------------------------------------
#define SMEM_BYTES 189440

__global__ __launch_bounds__(512, 1) void k_scan(const float* __restrict__ W,
                                                 const float* __restrict__ bias,
                                                 float* __restrict__ out,
                                                 int write_final) {
    extern __shared__ float sm[];
    float4* Ws4   = reinterpret_cast<float4*>(sm);        // [k*8 + ngrp]
    float*  WTs   = sm + 16384;                           // [k*36 + n]
    float*  xbuf  = sm + 34816;                           // [k*20 + m]
    float*  parts = sm + 45056;                           // [(kq*16+m)*36 + n]

    const int tid  = threadIdx.x;
    const int s    = blockIdx.x & 15;   // N-slice
    const int g    = blockIdx.x >> 4;   // batch group
    const int wrp  = tid >> 5;          // warp id = exchange slice owned
    const int lane = tid & 31;

    // GEMV mapping
    const int kq   = tid >> 7;
    const int rem  = tid & 127;
    const int mloc = rem >> 3;
    const int ngrp = rem & 7;
    const int kb   = kq << 7;

    // state mapping: thread owns (m, n)
    const int m = tid >> 5;
    const int n = tid & 31;

    // ---- prologue: load weight slices into SMEM ----
    {
        const float4* W4 = reinterpret_cast<const float4*>(W);
        #pragma unroll
        for (int j = 0; j < 8; j++) {           // Ws[k][n] = W[k][s*32+n]
            int f4 = tid + j * 512;
            int k  = f4 >> 3, ng = f4 & 7;
            Ws4[k * 8 + ng] = W4[(size_t)k * 128 + s * 8 + ng];
        }
        #pragma unroll
        for (int j = 0; j < 8; j++) {           // WTs[k][r] = W[s*32+r][k]
            int f4  = tid + j * 512;
            int r   = f4 >> 7;
            int kc4 = f4 & 127;
            float4 v = W4[(size_t)(s * 32 + r) * 128 + kc4];
            int k = kc4 * 4;
            WTs[(k + 0) * 36 + r] = v.x;
            WTs[(k + 1) * 36 + r] = v.y;
            WTs[(k + 2) * 36 + r] = v.z;
            WTs[(k + 3) * 36 + r] = v.w;
        }
    }
    const float bj = __ldg(bias + s * NS_ + n);
    float hy = 0.f, hz = 0.f;
    __syncthreads();

    const size_t io_base = ((size_t)(g * MG_ + m) * T_) * NH_ + s * NS_ + n;
    const float4* hySrc = reinterpret_cast<const float4*>(&g_hyT[g][0][0]) + wrp * 128;
    const float4* zSrc  = reinterpret_cast<const float4*>(&g_zT [g][0][0]) + wrp * 128;
    int* const fH = &g_flagH[g][wrp];
    int* const fZ = &g_flagZ[g][wrp];

    for (int t = 0; t < T_; t++) {
        const float inp = __ldg(&g_i2h[io_base + (size_t)t * NH_]);

        if (t == 0) {
            // hy = 0 => z[m][k] = tanh(bias[k]); fill locally, skip phase 1.
            for (int idx = tid; idx < NH_ * MG_; idx += 512) {
                int k = idx >> 4, mm = idx & 15;
                xbuf[k * 20 + mm] = tanhf(__ldg(bias + k));
            }
            __syncthreads();
        } else {
            // ---- gather hy(t-1): warp wrp waits for + loads slice wrp ----
            while (ld_acquire_gpu(fH) < t) { }
            #pragma unroll
            for (int j = 0; j < 4; j++) {
                int f4 = lane + j * 32;
                float4 v = __ldcg(hySrc + f4);
                int gf = wrp * 128 + f4;
                int kg = gf >> 2, mq = gf & 3;
                *reinterpret_cast<float4*>(&xbuf[kg * 20 + mq * 4]) = v;
            }
            __syncthreads();

            // ---- phase 1: a = hy @ W[:, slice] ----
            float4 acc = make_float4(0.f, 0.f, 0.f, 0.f);
            #pragma unroll 8
            for (int i = 0; i < 128; i++) {
                const int k = kb + i;
                float4 w = Ws4[k * 8 + ngrp];
                float  h = xbuf[k * 20 + mloc];
                acc.x = fmaf(h, w.x, acc.x); acc.y = fmaf(h, w.y, acc.y);
                acc.z = fmaf(h, w.z, acc.z); acc.w = fmaf(h, w.w, acc.w);
            }
            *reinterpret_cast<float4*>(&parts[(kq * 16 + mloc) * 36 + ngrp * 4]) = acc;
            __syncthreads();

            // reduce, tanh, publish z slice
            {
                float a = (parts[(0 * 16 + m) * 36 + n] + parts[(1 * 16 + m) * 36 + n])
                        + (parts[(2 * 16 + m) * 36 + n] + parts[(3 * 16 + m) * 36 + n]);
                __stcg(&g_zT[g][s * NS_ + n][m], tanhf(a + bj));
            }
            __syncthreads();
            if (tid == 0) st_release_gpu(&g_flagZ[g][s], t + 1);

            // ---- gather z(t): warp wrp waits for + loads slice wrp ----
            while (ld_acquire_gpu(fZ) < t + 1) { }
            #pragma unroll
            for (int j = 0; j < 4; j++) {
                int f4 = lane + j * 32;
                float4 v = __ldcg(zSrc + f4);
                int gf = wrp * 128 + f4;
                int kg = gf >> 2, mq = gf & 3;
                *reinterpret_cast<float4*>(&xbuf[kg * 20 + mq * 4]) = v;
            }
            __syncthreads();
        }

        // ---- phase 2: rec = z @ WT[:, slice] ----
        {
            float4 acc = make_float4(0.f, 0.f, 0.f, 0.f);
            #pragma unroll 8
            for (int i = 0; i < 128; i++) {
                const int k = kb + i;
                float4 w = *reinterpret_cast<const float4*>(&WTs[k * 36 + ngrp * 4]);
                float  z = xbuf[k * 20 + mloc];
                acc.x = fmaf(z, w.x, acc.x); acc.y = fmaf(z, w.y, acc.y);
                acc.z = fmaf(z, w.z, acc.z); acc.w = fmaf(z, w.w, acc.w);
            }
            *reinterpret_cast<float4*>(&parts[(kq * 16 + mloc) * 36 + ngrp * 4]) = acc;
        }
        __syncthreads();

        // reduce + state update (GAMMA = EPSILON = 1)
        {
            float rr = (parts[(0 * 16 + m) * 36 + n] + parts[(1 * 16 + m) * 36 + n])
                     + (parts[(2 * 16 + m) * 36 + n] + parts[(3 * 16 + m) * 36 + n]);
            hz += DT_C * (inp - rr - hy - hz);
            hy += DT_C * hz;
            out[io_base + (size_t)t * NH_] = hy;
            __stcg(&g_hyT[g][s * NS_ + n][m], hy);
        }
        __syncthreads();
        if (tid == 0) st_release_gpu(&g_flagH[g][s], t + 1);
    }

    if (write_final) {
        out[(size_t)B_ * T_ * NH_ + (size_t)(g * MG_ + m) * NH_ + s * NS_ + n] = hy;
    }
}

// ---------------------------------------------------------------------------
// Launch. Inputs: x [128,1024,64] f32, x2h [64,512] f32, h2h [512,512] f32,
// bias [512] f32. Output f32: all_states [128,1024,512] (+ hy_f [128,512]).
// ---------------------------------------------------------------------------
extern "C" void kernel_launch(void* const* d_in, const int* in_sizes, int n_in,
                              void* d_out, int out_size) {
    const float* x    = (const float*)d_in[0];
    const float* x2h  = (const float*)d_in[1];
    const float* h2h  = (const float*)d_in[2];
    const float* bias = (const float*)d_in[3];
    float* out = (float*)d_out;

    const long long states_elems = (long long)B_ * T_ * NH_;
    int write_final = ((long long)out_size >= states_elems + (long long)B_ * NH_) ? 1 : 0;

    cudaFuncSetAttribute(k_scan, cudaFuncAttributeMaxDynamicSharedMemorySize, SMEM_BYTES);

    k_i2h<<<dim3(NH_ / 64, (B_ * T_) / 64), 256>>>(x, x2h);
    k_scan<<<G_ * S_, 512, SMEM_BYTES>>>(h2h, bias, out, write_final);
}

// round 12
// speedup vs baseline: 1.6970x; 1.6970x over previous
#include <cuda_runtime.h>
#include <cstddef>
#include <cstdint>

#define B_   128
#define T_   1024
#define NI_  64
#define NH_  512
#define DT_C 0.01f

#define S_   16    // N-slices per batch group (CTAs per sync group)
#define NS_  32    // hidden cols per slice
#define G_   8     // batch groups
#define MG_  16    // batch rows per group

// __device__ scratch (allocation-free rule)
__device__ float g_i2h[(size_t)B_ * T_ * NH_];     // tanh(x @ x2h), [B][T][NH]
__device__ float g_hyT[G_][NH_][MG_];              // hy exchange, transposed [k][m]
__device__ float g_zT [G_][NH_][MG_];              // z  exchange, transposed [k][m]
__device__ int   g_flagH[G_][S_];
__device__ int   g_flagZ[G_][S_];

// ---- scoped release/acquire flag ops ----
__device__ __forceinline__ void st_release_gpu(int* p, int v) {
    asm volatile("st.release.gpu.b32 [%0], %1;" :: "l"(p), "r"(v) : "memory");
}
__device__ __forceinline__ int ld_acquire_gpu(const int* p) {
    int v;
    asm volatile("ld.acquire.gpu.b32 %0, [%1];" : "=r"(v) : "l"(p) : "memory");
    return v;
}

// ---------------------------------------------------------------------------
// i2h = tanh(x @ x2h).  x: [B*T, 64], x2h: [64, 512].
// Block (0,0) also resets the scan flags (stream order precedes k_scan).
// ---------------------------------------------------------------------------
__global__ __launch_bounds__(256) void k_i2h(const float* __restrict__ x,
                                             const float* __restrict__ x2h) {
    __shared__ float xsT[64][64];
    __shared__ float ws[64][64];
    int row0 = blockIdx.y * 64;
    int col0 = blockIdx.x * 64;
    int tid  = threadIdx.x;

    if (blockIdx.x == 0 && blockIdx.y == 0 && tid < G_ * S_) {
        ((int*)g_flagH)[tid] = 0;
        ((int*)g_flagZ)[tid] = 0;
    }

    const float4* xsrc = reinterpret_cast<const float4*>(x + (size_t)row0 * NI_);
    for (int i = tid; i < 1024; i += 256) {
        float4 v = xsrc[i];
        int m = i >> 4;
        int k = (i & 15) * 4;
        xsT[k + 0][m] = v.x; xsT[k + 1][m] = v.y;
        xsT[k + 2][m] = v.z; xsT[k + 3][m] = v.w;
    }
    for (int i = tid; i < 1024; i += 256) {
        int k = i >> 4;
        int c = (i & 15) * 4;
        float4 v = *reinterpret_cast<const float4*>(x2h + (size_t)k * NH_ + col0 + c);
        *reinterpret_cast<float4*>(&ws[k][c]) = v;
    }
    __syncthreads();

    int tx = tid & 15, ty = tid >> 4;
    int m0 = ty * 4, n0 = tx * 4;
    float acc[4][4] = {};
    #pragma unroll 4
    for (int k = 0; k < 64; k++) {
        float4 a = *reinterpret_cast<float4*>(&xsT[k][m0]);
        float4 b = *reinterpret_cast<float4*>(&ws[k][n0]);
        float av[4] = {a.x, a.y, a.z, a.w};
        float bv[4] = {b.x, b.y, b.z, b.w};
        #pragma unroll
        for (int i = 0; i < 4; i++)
            #pragma unroll
            for (int j = 0; j < 4; j++)
                acc[i][j] = fmaf(av[i], bv[j], acc[i][j]);
    }
    #pragma unroll
    for (int i = 0; i < 4; i++) {
        float4 o;
        o.x = tanhf(acc[i][0]); o.y = tanhf(acc[i][1]);
        o.z = tanhf(acc[i][2]); o.w = tanhf(acc[i][3]);
        *reinterpret_cast<float4*>(&g_i2h[(size_t)(row0 + m0 + i) * NH_ + col0 + n0]) = o;
    }
}

// ---------------------------------------------------------------------------
// Persistent scan: 128 CTAs = 8 batch groups x 16 N-slices, 512 threads.
// Weights SMEM-resident. Per-step hy/z exchange through small L2 buffers.
// Sync: ONE warp per CTA polls (16 threads, one flag each, ONE dependent
// LDG in flight -> self-paced ~300cyc, no nanosleep, no L1TEX flood).
// Publish: syncthreads + lone st.release.gpu.
//
// SMEM (floats): Ws[512][32] @0 | WTs[512][36] @16384 | xbuf[512][20] @34816
//                parts[4][16][36] @45056   -> 189440 bytes dynamic
// ---------------------------------------------------------------------------
#define SMEM_BYTES 189440

__global__ __launch_bounds__(512, 1) void k_scan(const float* __restrict__ W,
                                                 const float* __restrict__ bias,
                                                 float* __restrict__ out,
                                                 int write_final) {
    extern __shared__ float sm[];
    float4* Ws4   = reinterpret_cast<float4*>(sm);        // [k*8 + ngrp]
    float*  WTs   = sm + 16384;                           // [k*36 + n]
    float*  xbuf  = sm + 34816;                           // [k*20 + m]
    float*  parts = sm + 45056;                           // [(kq*16+m)*36 + n]

    const int tid = threadIdx.x;
    const int s   = blockIdx.x & 15;   // N-slice
    const int g   = blockIdx.x >> 4;   // batch group

    // GEMV mapping
    const int kq   = tid >> 7;
    const int rem  = tid & 127;
    const int mloc = rem >> 3;
    const int ngrp = rem & 7;
    const int kb   = kq << 7;

    // state mapping: thread owns (m, n)
    const int m = tid >> 5;
    const int n = tid & 31;

    // ---- prologue: load weight slices into SMEM ----
    {
        const float4* W4 = reinterpret_cast<const float4*>(W);
        #pragma unroll
        for (int j = 0; j < 8; j++) {           // Ws[k][n] = W[k][s*32+n]
            int f4 = tid + j * 512;
            int k  = f4 >> 3, ng = f4 & 7;
            Ws4[k * 8 + ng] = W4[(size_t)k * 128 + s * 8 + ng];
        }
        #pragma unroll
        for (int j = 0; j < 8; j++) {           // WTs[k][r] = W[s*32+r][k]
            int f4  = tid + j * 512;
            int r   = f4 >> 7;
            int kc4 = f4 & 127;
            float4 v = W4[(size_t)(s * 32 + r) * 128 + kc4];
            int k = kc4 * 4;
            WTs[(k + 0) * 36 + r] = v.x;
            WTs[(k + 1) * 36 + r] = v.y;
            WTs[(k + 2) * 36 + r] = v.z;
            WTs[(k + 3) * 36 + r] = v.w;
        }
    }
    const float bj = __ldg(bias + s * NS_ + n);
    float hy = 0.f, hz = 0.f;
    __syncthreads();

    const size_t io_base = ((size_t)(g * MG_ + m) * T_) * NH_ + s * NS_ + n;
    const float4* hySrc = reinterpret_cast<const float4*>(&g_hyT[g][0][0]);
    const float4* zSrc  = reinterpret_cast<const float4*>(&g_zT [g][0][0]);
    int* const fH = (tid < S_) ? &g_flagH[g][tid] : nullptr;
    int* const fZ = (tid < S_) ? &g_flagZ[g][tid] : nullptr;

    for (int t = 0; t < T_; t++) {
        const float inp = __ldg(&g_i2h[io_base + (size_t)t * NH_]);

        if (t == 0) {
            // hy = 0 => z[m][k] = tanh(bias[k]); fill locally, skip phase 1.
            for (int idx = tid; idx < NH_ * MG_; idx += 512) {
                int k = idx >> 4, mm = idx & 15;
                xbuf[k * 20 + mm] = tanhf(__ldg(bias + k));
            }
            __syncthreads();
        } else {
            // ---- wait for all hy slices (warp-0 poll, self-paced by L2 lat)
            if (tid < S_) { while (ld_acquire_gpu(fH) < t) { } }
            __syncthreads();
            // ---- gather hy(t-1), all threads ----
            #pragma unroll
            for (int j = 0; j < 4; j++) {
                int f4 = tid + j * 512;            // 2048 float4
                float4 v = __ldcg(hySrc + f4);
                int kg = f4 >> 2, mq = f4 & 3;
                *reinterpret_cast<float4*>(&xbuf[kg * 20 + mq * 4]) = v;
            }
            __syncthreads();

            // ---- phase 1: a = hy @ W[:, slice] ----
            float4 acc = make_float4(0.f, 0.f, 0.f, 0.f);
            #pragma unroll 8
            for (int i = 0; i < 128; i++) {
                const int k = kb + i;
                float4 w = Ws4[k * 8 + ngrp];
                float  h = xbuf[k * 20 + mloc];
                acc.x = fmaf(h, w.x, acc.x); acc.y = fmaf(h, w.y, acc.y);
                acc.z = fmaf(h, w.z, acc.z); acc.w = fmaf(h, w.w, acc.w);
            }
            *reinterpret_cast<float4*>(&parts[(kq * 16 + mloc) * 36 + ngrp * 4]) = acc;
            __syncthreads();

            // reduce, tanh, publish z slice
            {
                float a = (parts[(0 * 16 + m) * 36 + n] + parts[(1 * 16 + m) * 36 + n])
                        + (parts[(2 * 16 + m) * 36 + n] + parts[(3 * 16 + m) * 36 + n]);
                __stcg(&g_zT[g][s * NS_ + n][m], tanhf(a + bj));
            }
            __syncthreads();
            if (tid == 0) st_release_gpu(&g_flagZ[g][s], t + 1);

            // ---- wait for all z slices ----
            if (tid < S_) { while (ld_acquire_gpu(fZ) < t + 1) { } }
            __syncthreads();
            // ---- gather z(t), all threads ----
            #pragma unroll
            for (int j = 0; j < 4; j++) {
                int f4 = tid + j * 512;
                float4 v = __ldcg(zSrc + f4);
                int kg = f4 >> 2, mq = f4 & 3;
                *reinterpret_cast<float4*>(&xbuf[kg * 20 + mq * 4]) = v;
            }
            __syncthreads();
        }

        // ---- phase 2: rec = z @ WT[:, slice] ----
        {
            float4 acc = make_float4(0.f, 0.f, 0.f, 0.f);
            #pragma unroll 8
            for (int i = 0; i < 128; i++) {
                const int k = kb + i;
                float4 w = *reinterpret_cast<const float4*>(&WTs[k * 36 + ngrp * 4]);
                float  z = xbuf[k * 20 + mloc];
                acc.x = fmaf(z, w.x, acc.x); acc.y = fmaf(z, w.y, acc.y);
                acc.z = fmaf(z, w.z, acc.z); acc.w = fmaf(z, w.w, acc.w);
            }
            *reinterpret_cast<float4*>(&parts[(kq * 16 + mloc) * 36 + ngrp * 4]) = acc;
        }
        __syncthreads();

        // reduce + state update (GAMMA = EPSILON = 1)
        {
            float rr = (parts[(0 * 16 + m) * 36 + n] + parts[(1 * 16 + m) * 36 + n])
                     + (parts[(2 * 16 + m) * 36 + n] + parts[(3 * 16 + m) * 36 + n]);
            hz += DT_C * (inp - rr - hy - hz);
            hy += DT_C * hz;
            __stcg(&g_hyT[g][s * NS_ + n][m], hy);
            out[io_base + (size_t)t * NH_] = hy;
        }
        __syncthreads();
        if (tid == 0) st_release_gpu(&g_flagH[g][s], t + 1);
    }

    if (write_final) {
        out[(size_t)B_ * T_ * NH_ + (size_t)(g * MG_ + m) * NH_ + s * NS_ + n] = hy;
    }
}

// ---------------------------------------------------------------------------
// Launch. Inputs: x [128,1024,64] f32, x2h [64,512] f32, h2h [512,512] f32,
// bias [512] f32. Output f32: all_states [128,1024,512] (+ hy_f [128,512]).
// ---------------------------------------------------------------------------
extern "C" void kernel_launch(void* const* d_in, const int* in_sizes, int n_in,
                              void* d_out, int out_size) {
    const float* x    = (const float*)d_in[0];
    const float* x2h  = (const float*)d_in[1];
    const float* h2h  = (const float*)d_in[2];
    const float* bias = (const float*)d_in[3];
    float* out = (float*)d_out;

    const long long states_elems = (long long)B_ * T_ * NH_;
    int write_final = ((long long)out_size >= states_elems + (long long)B_ * NH_) ? 1 : 0;

    cudaFuncSetAttribute(k_scan, cudaFuncAttributeMaxDynamicSharedMemorySize, SMEM_BYTES);

    k_i2h<<<dim3(NH_ / 64, (B_ * T_) / 64), 256>>>(x, x2h);
    k_scan<<<G_ * S_, 512, SMEM_BYTES>>>(h2h, bias, out, write_final);
}

// round 13
// speedup vs baseline: 2.4781x; 1.4603x over previous
#include <cuda_runtime.h>
#include <cstddef>
#include <cstdint>

#define B_   128
#define T_   1024
#define NI_  64
#define NH_  512
#define DT_C 0.01f

#define S_   16    // N-slices per batch group (CTAs per sync group)
#define NS_  32    // hidden cols per slice
#define G_   8     // batch groups
#define MG_  16    // batch rows per group

// __device__ scratch (allocation-free rule)
__device__ float g_i2h[(size_t)B_ * T_ * NH_];     // tanh(x @ x2h), [B][T][NH]
__device__ float g_hyT[G_][NH_][MG_];              // hy exchange, [k][m]
__device__ float g_zT [G_][NH_][MG_];              // z  exchange, [k][m]
__device__ int   g_flagH[G_][S_];
__device__ int   g_flagZ[G_][S_];

// ---- scoped release/acquire flag ops ----
__device__ __forceinline__ void st_release_gpu(int* p, int v) {
    asm volatile("st.release.gpu.b32 [%0], %1;" :: "l"(p), "r"(v) : "memory");
}
__device__ __forceinline__ int ld_acquire_gpu(const int* p) {
    int v;
    asm volatile("ld.acquire.gpu.b32 %0, [%1];" : "=r"(v) : "l"(p) : "memory");
    return v;
}

// ---------------------------------------------------------------------------
// i2h = tanh(x @ x2h).  x: [B*T, 64], x2h: [64, 512].
// Block (0,0) also resets the scan flags (stream order precedes k_scan).
// ---------------------------------------------------------------------------
__global__ __launch_bounds__(256) void k_i2h(const float* __restrict__ x,
                                             const float* __restrict__ x2h) {
    __shared__ float xsT[64][64];
    __shared__ float ws[64][64];
    int row0 = blockIdx.y * 64;
    int col0 = blockIdx.x * 64;
    int tid  = threadIdx.x;

    if (blockIdx.x == 0 && blockIdx.y == 0 && tid < G_ * S_) {
        ((int*)g_flagH)[tid] = 0;
        ((int*)g_flagZ)[tid] = 0;
    }

    const float4* xsrc = reinterpret_cast<const float4*>(x + (size_t)row0 * NI_);
    for (int i = tid; i < 1024; i += 256) {
        float4 v = xsrc[i];
        int m = i >> 4;
        int k = (i & 15) * 4;
        xsT[k + 0][m] = v.x; xsT[k + 1][m] = v.y;
        xsT[k + 2][m] = v.z; xsT[k + 3][m] = v.w;
    }
    for (int i = tid; i < 1024; i += 256) {
        int k = i >> 4;
        int c = (i & 15) * 4;
        float4 v = *reinterpret_cast<const float4*>(x2h + (size_t)k * NH_ + col0 + c);
        *reinterpret_cast<float4*>(&ws[k][c]) = v;
    }
    __syncthreads();

    int tx = tid & 15, ty = tid >> 4;
    int m0 = ty * 4, n0 = tx * 4;
    float acc[4][4] = {};
    #pragma unroll 4
    for (int k = 0; k < 64; k++) {
        float4 a = *reinterpret_cast<float4*>(&xsT[k][m0]);
        float4 b = *reinterpret_cast<float4*>(&ws[k][n0]);
        float av[4] = {a.x, a.y, a.z, a.w};
        float bv[4] = {b.x, b.y, b.z, b.w};
        #pragma unroll
        for (int i = 0; i < 4; i++)
            #pragma unroll
            for (int j = 0; j < 4; j++)
                acc[i][j] = fmaf(av[i], bv[j], acc[i][j]);
    }
    #pragma unroll
    for (int i = 0; i < 4; i++) {
        float4 o;
        o.x = tanhf(acc[i][0]); o.y = tanhf(acc[i][1]);
        o.z = tanhf(acc[i][2]); o.w = tanhf(acc[i][3]);
        *reinterpret_cast<float4*>(&g_i2h[(size_t)(row0 + m0 + i) * NH_ + col0 + n0]) = o;
    }
}

// ---------------------------------------------------------------------------
// Persistent scan: 128 CTAs = 8 batch groups x 16 N-slices, 512 threads.
// Weights SMEM-resident. GEMV micro-tile: 4 rows x 4 cols x K-chunk(32)
// per thread -> 16 FMA per 2x LDS.128 (4x fewer smem wavefronts than R12).
// Sync: one warp polls 16 flags (acquire), publish via smem-transpose stage
// -> coalesced STG.128 -> barrier -> lone st.release.
//
// SMEM floats: Ws4 @0 (16384) | WTs @16384 (18432, [k][36]) |
//              xbuf @34816 (8192, [k][m] f4) | parts @43008 (9216) |
//              staging @52224 (544)  => 52768 floats = 211072 B
// ---------------------------------------------------------------------------
#define SMEM_BYTES 211072

__global__ __launch_bounds__(512, 1) void k_scan(const float* __restrict__ W,
                                                 const float* __restrict__ bias,
                                                 float* __restrict__ out,
                                                 int write_final) {
    extern __shared__ float sm[];
    float4* Ws4     = reinterpret_cast<float4*>(sm);      // [k*8 + ng]
    float*  WTs     = sm + 16384;                         // [k*36 + r]
    float*  xbuf    = sm + 34816;                         // [k][m], f4-readable
    float4* xb4     = reinterpret_cast<float4*>(xbuf);    // [k*4 + mq]
    float*  parts   = sm + 43008;                         // [(kc*16+mrow)*36 + n]
    float*  staging = sm + 52224;                         // [n*17 + m]

    const int tid = threadIdx.x;
    const int s   = blockIdx.x & 15;   // N-slice
    const int g   = blockIdx.x >> 4;   // batch group

    // GEMV micro-tile mapping: warp = one K-chunk of 32
    const int kc = tid >> 5;           // K-chunk 0..15
    const int mq = (tid >> 3) & 3;     // row quad 0..3
    const int ng = tid & 7;            // col group 0..7
    const int k0 = kc << 5;

    // state mapping: thread owns (m, n)
    const int m = tid >> 5;
    const int n = tid & 31;

    // ---- prologue: load weight slices into SMEM ----
    {
        const float4* W4 = reinterpret_cast<const float4*>(W);
        #pragma unroll
        for (int j = 0; j < 8; j++) {           // Ws[k][c] = W[k][s*32+c]
            int f4 = tid + j * 512;
            int k  = f4 >> 3, c = f4 & 7;
            Ws4[k * 8 + c] = W4[(size_t)k * 128 + s * 8 + c];
        }
        #pragma unroll
        for (int j = 0; j < 8; j++) {           // WTs[k][r] = W[s*32+r][k]
            int f4  = tid + j * 512;
            int r   = f4 >> 7;
            int kc4 = f4 & 127;
            float4 v = W4[(size_t)(s * 32 + r) * 128 + kc4];
            int k = kc4 * 4;
            WTs[(k + 0) * 36 + r] = v.x;
            WTs[(k + 1) * 36 + r] = v.y;
            WTs[(k + 2) * 36 + r] = v.z;
            WTs[(k + 3) * 36 + r] = v.w;
        }
    }
    const float bj = __ldg(bias + s * NS_ + n);
    float hy = 0.f, hz = 0.f;
    __syncthreads();

    const size_t io_base = ((size_t)(g * MG_ + m) * T_) * NH_ + s * NS_ + n;
    const float4* hySrc = reinterpret_cast<const float4*>(&g_hyT[g][0][0]);
    const float4* zSrc  = reinterpret_cast<const float4*>(&g_zT [g][0][0]);
    float4* hyDst = reinterpret_cast<float4*>(&g_hyT[g][s * NS_][0]);  // 128 f4
    float4* zDst  = reinterpret_cast<float4*>(&g_zT [g][s * NS_][0]);
    int* const fH = (tid < S_) ? &g_flagH[g][tid] : nullptr;
    int* const fZ = (tid < S_) ? &g_flagZ[g][tid] : nullptr;

    for (int t = 0; t < T_; t++) {
        const float inp = __ldg(&g_i2h[io_base + (size_t)t * NH_]);

        if (t == 0) {
            // hy=0 => z[k] = tanh(bias[k]) for all m; fill locally, skip phase1.
            #pragma unroll
            for (int j = 0; j < 4; j++) {
                int f4 = tid + j * 512;            // [k*4 + mq]
                float v = tanhf(__ldg(bias + (f4 >> 2)));
                xb4[f4] = make_float4(v, v, v, v);
            }
            __syncthreads();
        } else {
            // ---- wait for all hy slices (single-warp poll) + gather ----
            if (tid < S_) { while (ld_acquire_gpu(fH) < t) { } }
            __syncthreads();
            #pragma unroll
            for (int j = 0; j < 4; j++) {
                int f4 = tid + j * 512;
                xb4[f4] = __ldcg(hySrc + f4);
            }
            __syncthreads();

            // ---- phase 1: a = hy @ W[:, slice]  (4r x 4c x K32 tile) ----
            float4 a0 = make_float4(0.f,0.f,0.f,0.f), a1 = a0, a2 = a0, a3 = a0;
            #pragma unroll
            for (int i = 0; i < 32; i++) {
                const int k = k0 + i;
                float4 w = Ws4[k * 8 + ng];
                float4 h = xb4[k * 4 + mq];
                a0.x = fmaf(h.x, w.x, a0.x); a0.y = fmaf(h.x, w.y, a0.y);
                a0.z = fmaf(h.x, w.z, a0.z); a0.w = fmaf(h.x, w.w, a0.w);
                a1.x = fmaf(h.y, w.x, a1.x); a1.y = fmaf(h.y, w.y, a1.y);
                a1.z = fmaf(h.y, w.z, a1.z); a1.w = fmaf(h.y, w.w, a1.w);
                a2.x = fmaf(h.z, w.x, a2.x); a2.y = fmaf(h.z, w.y, a2.y);
                a2.z = fmaf(h.z, w.z, a2.z); a2.w = fmaf(h.z, w.w, a2.w);
                a3.x = fmaf(h.w, w.x, a3.x); a3.y = fmaf(h.w, w.y, a3.y);
                a3.z = fmaf(h.w, w.z, a3.z); a3.w = fmaf(h.w, w.w, a3.w);
            }
            {
                float* pb = &parts[(kc * 16 + mq * 4) * 36 + ng * 4];
                *reinterpret_cast<float4*>(pb + 0 * 36) = a0;
                *reinterpret_cast<float4*>(pb + 1 * 36) = a1;
                *reinterpret_cast<float4*>(pb + 2 * 36) = a2;
                *reinterpret_cast<float4*>(pb + 3 * 36) = a3;
            }
            __syncthreads();

            // reduce 16 partials, tanh, stage transposed
            {
                float a = 0.f;
                #pragma unroll
                for (int q = 0; q < 16; q++) a += parts[(q * 16 + m) * 36 + n];
                staging[n * 17 + m] = tanhf(a + bj);
            }
            __syncthreads();
            if (tid < 128) {                       // coalesced publish: 2KB
                int nn = tid >> 2, m0 = (tid & 3) * 4;
                const float* sp = &staging[nn * 17 + m0];
                __stcg(zDst + tid, make_float4(sp[0], sp[1], sp[2], sp[3]));
            }
            __syncthreads();
            if (tid == 0) st_release_gpu(&g_flagZ[g][s], t + 1);

            // ---- wait for all z slices + gather ----
            if (tid < S_) { while (ld_acquire_gpu(fZ) < t + 1) { } }
            __syncthreads();
            #pragma unroll
            for (int j = 0; j < 4; j++) {
                int f4 = tid + j * 512;
                xb4[f4] = __ldcg(zSrc + f4);
            }
            __syncthreads();
        }

        // ---- phase 2: rec = z @ WT[:, slice] ----
        {
            float4 a0 = make_float4(0.f,0.f,0.f,0.f), a1 = a0, a2 = a0, a3 = a0;
            #pragma unroll
            for (int i = 0; i < 32; i++) {
                const int k = k0 + i;
                float4 w = *reinterpret_cast<const float4*>(&WTs[k * 36 + ng * 4]);
                float4 z = xb4[k * 4 + mq];
                a0.x = fmaf(z.x, w.x, a0.x); a0.y = fmaf(z.x, w.y, a0.y);
                a0.z = fmaf(z.x, w.z, a0.z); a0.w = fmaf(z.x, w.w, a0.w);
                a1.x = fmaf(z.y, w.x, a1.x); a1.y = fmaf(z.y, w.y, a1.y);
                a1.z = fmaf(z.y, w.z, a1.z); a1.w = fmaf(z.y, w.w, a1.w);
                a2.x = fmaf(z.z, w.x, a2.x); a2.y = fmaf(z.z, w.y, a2.y);
                a2.z = fmaf(z.z, w.z, a2.z); a2.w = fmaf(z.z, w.w, a2.w);
                a3.x = fmaf(z.w, w.x, a3.x); a3.y = fmaf(z.w, w.y, a3.y);
                a3.z = fmaf(z.w, w.z, a3.z); a3.w = fmaf(z.w, w.w, a3.w);
            }
            float* pb = &parts[(kc * 16 + mq * 4) * 36 + ng * 4];
            *reinterpret_cast<float4*>(pb + 0 * 36) = a0;
            *reinterpret_cast<float4*>(pb + 1 * 36) = a1;
            *reinterpret_cast<float4*>(pb + 2 * 36) = a2;
            *reinterpret_cast<float4*>(pb + 3 * 36) = a3;
        }
        __syncthreads();

        // reduce + state update (GAMMA = EPSILON = 1), stage hy
        {
            float rr = 0.f;
            #pragma unroll
            for (int q = 0; q < 16; q++) rr += parts[(q * 16 + m) * 36 + n];
            hz += DT_C * (inp - rr - hy - hz);
            hy += DT_C * hz;
            staging[n * 17 + m] = hy;
        }
        __syncthreads();
        if (tid < 128) {                           // coalesced publish: 2KB
            int nn = tid >> 2, m0 = (tid & 3) * 4;
            const float* sp = &staging[nn * 17 + m0];
            __stcg(hyDst + tid, make_float4(sp[0], sp[1], sp[2], sp[3]));
        }
        __syncthreads();
        if (tid == 0) st_release_gpu(&g_flagH[g][s], t + 1);

        // out store AFTER release: off the group-wide critical path
        out[io_base + (size_t)t * NH_] = hy;
    }

    if (write_final) {
        out[(size_t)B_ * T_ * NH_ + (size_t)(g * MG_ + m) * NH_ + s * NS_ + n] = hy;
    }
}

// ---------------------------------------------------------------------------
// Launch. Inputs: x [128,1024,64] f32, x2h [64,512] f32, h2h [512,512] f32,
// bias [512] f32. Output f32: all_states [128,1024,512] (+ hy_f [128,512]).
// ---------------------------------------------------------------------------
extern "C" void kernel_launch(void* const* d_in, const int* in_sizes, int n_in,
                              void* d_out, int out_size) {
    const float* x    = (const float*)d_in[0];
    const float* x2h  = (const float*)d_in[1];
    const float* h2h  = (const float*)d_in[2];
    const float* bias = (const float*)d_in[3];
    float* out = (float*)d_out;

    const long long states_elems = (long long)B_ * T_ * NH_;
    int write_final = ((long long)out_size >= states_elems + (long long)B_ * NH_) ? 1 : 0;

    cudaFuncSetAttribute(k_scan, cudaFuncAttributeMaxDynamicSharedMemorySize, SMEM_BYTES);

    k_i2h<<<dim3(NH_ / 64, (B_ * T_) / 64), 256>>>(x, x2h);
    k_scan<<<G_ * S_, 512, SMEM_BYTES>>>(h2h, bias, out, write_final);
}